// round 3
// baseline (speedup 1.0000x reference)
#include <cuda_runtime.h>
#include <cuda_bf16.h>

#define NN 100000
#define EE 1600000
#define BB 256

// ---- scratch (device globals; no allocation allowed) ----
__device__ __align__(128) float g_h[(size_t)NN * 128];    // hs = (A @ W) * dis[n]
__device__ __align__(128) float g_act[(size_t)NN * 128];  // layer activations
__device__ __align__(128) float g_agg[(size_t)NN * 128];  // scatter accumulator
__device__ __align__(128) float g_dis[NN];                // deg -> rsqrt(deg+1)
__device__ int   g_src[EE];
__device__ int   g_dst[EE];
__device__ __align__(128) float g_sums[BB * 128];
__device__ float g_cnt[BB];
__device__ int   g_is64;   // 1 if integer inputs are stored as int64

__device__ __forceinline__ void red_add_v4(float* addr, float4 v) {
    unsigned long long ga = (unsigned long long)__cvta_generic_to_global(addr);
    asm volatile("red.global.add.v4.f32 [%0], {%1,%2,%3,%4};"
                 :: "l"(ga), "f"(v.x), "f"(v.y), "f"(v.z), "f"(v.w) : "memory");
}

// load integer index i from a buffer whose storage dtype is int32 or int64
__device__ __forceinline__ int load_idx(const void* p, long long i) {
    return g_is64 ? (int)((const long long*)p)[i] : ((const int*)p)[i];
}

// ---- dtype detector: int64 storage of values < 2^31 has all-odd words == 0 ----
__global__ void k_detect(const int* __restrict__ raw) {
    if (threadIdx.x == 0 && blockIdx.x == 0) {
        int nz = 0;
        for (int i = 1; i < 256; i += 2) nz += (raw[i] != 0);
        g_is64 = (nz == 0) ? 1 : 0;
    }
}

// ---- zero kernels ----
__global__ void k_zero_dis() {
    int i = blockIdx.x * blockDim.x + threadIdx.x;
    if (i < NN) g_dis[i] = 0.f;
}
__global__ void k_zero_agg(int n4) {
    int i = blockIdx.x * blockDim.x + threadIdx.x;
    if (i < n4) reinterpret_cast<float4*>(g_agg)[i] = make_float4(0.f, 0.f, 0.f, 0.f);
}
__global__ void k_zero_pool() {
    int i = blockIdx.x * blockDim.x + threadIdx.x;
    if (i < BB * 128) g_sums[i] = 0.f;
    if (i < BB) g_cnt[i] = 0.f;
}

// ---- edge preprocessing: dtype-agnostic load + in-degree count ----
__global__ void k_prep(const void* __restrict__ ei) {
    int e = blockIdx.x * blockDim.x + threadIdx.x;
    if (e >= EE) return;
    int s = load_idx(ei, e);
    int d = load_idx(ei, (long long)EE + e);
    if ((unsigned)s >= NN) s = 0;   // guard: degrade to wrong-answer, not IMA
    if ((unsigned)d >= NN) d = 0;
    g_src[e] = s;
    g_dst[e] = d;
    atomicAdd(&g_dis[d], 1.f);
}
__global__ void k_dis() {
    int n = blockIdx.x * blockDim.x + threadIdx.x;
    if (n < NN) g_dis[n] = rsqrtf(g_dis[n] + 1.f);
}

// ---- GEMM: g_h[n,:] = (A[n,:] @ W) * dis[n] ----
template <int FIN, int FOUT, int NPB, bool FROM_ACT>
__global__ void k_gemm(const float* __restrict__ Aext, const float* __restrict__ W) {
    const float* __restrict__ A = FROM_ACT ? (const float*)g_act : Aext;
    __shared__ float sW[FIN * FOUT];
    __shared__ float sX[NPB * FIN];
    const int tid = threadIdx.x;
    for (int i = tid; i < FIN * FOUT; i += 256) sW[i] = W[i];
    const int n0 = blockIdx.x * NPB;
    for (int i = tid; i < NPB * FIN; i += 256) {
        int nn = i / FIN, k = i % FIN;
        int n = n0 + nn;
        sX[i] = (n < NN) ? A[(size_t)n * FIN + k] : 0.f;
    }
    __syncthreads();
    const int f = tid % FOUT;
    const int r = tid / FOUT;
    const int NPI = 256 / FOUT;
    for (int nn = r; nn < NPB; nn += NPI) {
        int n = n0 + nn;
        if (n >= NN) continue;
        float s = 0.f;
        #pragma unroll
        for (int k = 0; k < FIN; k++) s = fmaf(sX[nn * FIN + k], sW[k * FOUT + f], s);
        g_h[(size_t)n * FOUT + f] = s * g_dis[n];
    }
}

// ---- scatter: agg[dst] += hs[src]  (per-edge norm already folded into hs) ----
__global__ void k_scatter64() {
    int t = blockIdx.x * blockDim.x + threadIdx.x;
    int e = t >> 4;
    if (e >= EE) return;
    int c = t & 15;
    int s = g_src[e], d = g_dst[e];
    float4 v = *reinterpret_cast<const float4*>(g_h + (size_t)s * 64 + c * 4);
    red_add_v4(g_agg + (size_t)d * 64 + c * 4, v);
}
__global__ void k_scatter128() {
    int t = blockIdx.x * blockDim.x + threadIdx.x;
    int e = t >> 5;
    if (e >= EE) return;
    int c = t & 31;
    int s = g_src[e], d = g_dst[e];
    float4 v = *reinterpret_cast<const float4*>(g_h + (size_t)s * 128 + c * 4);
    red_add_v4(g_agg + (size_t)d * 128 + c * 4, v);
}

// ---- epilogue layers 1/2: act = relu(bn(dis*(agg+hs) + b)) ----
__global__ void k_epi64(const float* __restrict__ b, const float* __restrict__ g,
                        const float* __restrict__ be, const float* __restrict__ m,
                        const float* __restrict__ v) {
    int i = blockIdx.x * blockDim.x + threadIdx.x;
    if (i >= NN * 64) return;
    int n = i >> 6, f = i & 63;
    float val = g_dis[n] * (g_agg[i] + g_h[i]) + b[f];
    float sc = g[f] * rsqrtf(v[f] + 1e-5f);
    val = (val - m[f]) * sc + be[f];
    g_act[i] = fmaxf(val, 0.f);
}

// ---- per-graph node counts ----
__global__ void k_cnt(const void* __restrict__ batch) {
    int n = blockIdx.x * blockDim.x + threadIdx.x;
    if (n >= NN) return;
    int bg = load_idx(batch, n);
    if ((unsigned)bg >= BB) bg = 0;
    atomicAdd(&g_cnt[bg], 1.f);
}

// ---- layer-3 epilogue fused with mean-pool accumulation ----
__global__ void k_epi3(const float* __restrict__ b3, const void* __restrict__ batch) {
    int t = blockIdx.x * blockDim.x + threadIdx.x;
    int n = t >> 5;
    if (n >= NN) return;
    int c = t & 31;
    int i = n * 128 + c * 4;
    float dis = g_dis[n];
    float4 a = *reinterpret_cast<const float4*>(g_agg + i);
    float4 h = *reinterpret_cast<const float4*>(g_h + i);
    float4 o;
    o.x = fmaxf(dis * (a.x + h.x) + b3[c * 4 + 0], 0.f);
    o.y = fmaxf(dis * (a.y + h.y) + b3[c * 4 + 1], 0.f);
    o.z = fmaxf(dis * (a.z + h.z) + b3[c * 4 + 2], 0.f);
    o.w = fmaxf(dis * (a.w + h.w) + b3[c * 4 + 3], 0.f);
    int bg = load_idx(batch, n);
    if ((unsigned)bg >= BB) bg = 0;
    red_add_v4(g_sums + bg * 128 + c * 4, o);
}

// ---- finalize: out[b,f] = sums / max(cnt, 1) ----
__global__ void k_final(float* __restrict__ out) {
    int i = blockIdx.x * blockDim.x + threadIdx.x;
    if (i >= BB * 128) return;
    out[i] = g_sums[i] / fmaxf(g_cnt[i >> 7], 1.f);
}

extern "C" void kernel_launch(void* const* d_in, const int* in_sizes, int n_in,
                              void* d_out, int out_size) {
    const float* x   = (const float*)d_in[0];
    const void*  ei  = d_in[1];
    const void*  bat = d_in[2];
    const float* W1 = (const float*)d_in[3];
    const float* b1 = (const float*)d_in[4];
    const float* W2 = (const float*)d_in[5];
    const float* b2 = (const float*)d_in[6];
    const float* W3 = (const float*)d_in[7];
    const float* b3 = (const float*)d_in[8];
    const float* g1 = (const float*)d_in[9];
    const float* be1 = (const float*)d_in[10];
    const float* m1 = (const float*)d_in[11];
    const float* v1 = (const float*)d_in[12];
    const float* g2 = (const float*)d_in[13];
    const float* be2 = (const float*)d_in[14];
    const float* m2 = (const float*)d_in[15];
    const float* v2 = (const float*)d_in[16];

    const int TB = 256;

    // dtype detection + degree / normalization
    k_detect<<<1, 32>>>((const int*)ei);
    k_zero_dis<<<(NN + TB - 1) / TB, TB>>>();
    k_prep<<<(EE + TB - 1) / TB, TB>>>(ei);
    k_dis<<<(NN + TB - 1) / TB, TB>>>();

    // ---- layer 1: 22 -> 64 ----
    k_zero_agg<<<(NN * 16 + TB - 1) / TB, TB>>>(NN * 16);
    k_gemm<22, 64, 16, false><<<(NN + 15) / 16, TB>>>(x, W1);
    k_scatter64<<<(EE * 16 + TB - 1) / TB, TB>>>();
    k_epi64<<<(NN * 64 + TB - 1) / TB, TB>>>(b1, g1, be1, m1, v1);

    // ---- layer 2: 64 -> 64 ----
    k_zero_agg<<<(NN * 16 + TB - 1) / TB, TB>>>(NN * 16);
    k_gemm<64, 64, 16, true><<<(NN + 15) / 16, TB>>>(nullptr, W2);
    k_scatter64<<<(EE * 16 + TB - 1) / TB, TB>>>();
    k_epi64<<<(NN * 64 + TB - 1) / TB, TB>>>(b2, g2, be2, m2, v2);

    // ---- layer 3: 64 -> 128, fused pooling ----
    k_zero_agg<<<(NN * 32 + TB - 1) / TB, TB>>>(NN * 32);
    k_gemm<64, 128, 8, true><<<(NN + 7) / 8, TB>>>(nullptr, W3);
    k_scatter128<<<(int)(((long long)EE * 32 + TB - 1) / TB), TB>>>();
    k_zero_pool<<<(BB * 128 + TB - 1) / TB, TB>>>();
    k_cnt<<<(NN + TB - 1) / TB, TB>>>(bat);
    k_epi3<<<(NN * 32 + TB - 1) / TB, TB>>>(b3, bat);
    k_final<<<(BB * 128 + TB - 1) / TB, TB>>>((float*)d_out);
}

// round 4
// speedup vs baseline: 1.3159x; 1.3159x over previous
#include <cuda_runtime.h>
#include <cuda_bf16.h>

#define NN 100000
#define EE 1600000
#define BB 256

// ---- scratch (device globals; no allocation allowed) ----
__device__ __align__(128) float g_h[(size_t)NN * 128];    // hs = (A @ W) * dis[n]
__device__ __align__(128) float g_act[(size_t)NN * 128];  // layer activations
__device__ __align__(128) float g_agg[(size_t)NN * 128];  // accumulator (init = hs)
__device__ __align__(128) float g_dis[NN];                // deg -> rsqrt(deg+1)
__device__ __align__(128) int2  g_edge[EE];               // packed {src, dst}
__device__ __align__(128) float g_sums[BB * 128];
__device__ float g_cnt[BB];
__device__ int   g_is64;   // 1 if integer inputs are stored as int64

__device__ __forceinline__ void red_add_v4(float* addr, float4 v) {
    unsigned long long ga = (unsigned long long)__cvta_generic_to_global(addr);
    asm volatile("red.global.add.v4.f32 [%0], {%1,%2,%3,%4};"
                 :: "l"(ga), "f"(v.x), "f"(v.y), "f"(v.z), "f"(v.w) : "memory");
}

__device__ __forceinline__ int load_idx(const void* p, long long i) {
    return g_is64 ? (int)((const long long*)p)[i] : ((const int*)p)[i];
}

// ---- init: zero degree array + dtype detection (block 0, thread 0) ----
__global__ void k_init(const int* __restrict__ raw) {
    int i = blockIdx.x * blockDim.x + threadIdx.x;
    if (i < NN) g_dis[i] = 0.f;
    if (i == 0) {
        int nz = 0;
        for (int j = 1; j < 256; j += 2) nz += (raw[j] != 0);
        g_is64 = (nz == 0) ? 1 : 0;
    }
}

// ---- edge preprocessing: pack indices + in-degree count ----
__global__ void k_prep(const void* __restrict__ ei) {
    int e = blockIdx.x * blockDim.x + threadIdx.x;
    if (e >= EE) return;
    int s = load_idx(ei, e);
    int d = load_idx(ei, (long long)EE + e);
    if ((unsigned)s >= NN) s = 0;
    if ((unsigned)d >= NN) d = 0;
    g_edge[e] = make_int2(s, d);
    atomicAdd(&g_dis[d], 1.f);
}

// ---- dis = rsqrt(deg+1); also zero the pooling buffers ----
__global__ void k_dis() {
    int n = blockIdx.x * blockDim.x + threadIdx.x;
    if (n < NN) g_dis[n] = rsqrtf(g_dis[n] + 1.f);
    if (n < BB * 128) g_sums[n] = 0.f;
    if (n < BB) g_cnt[n] = 0.f;
}

// ---- GEMM: hs[n,:] = (A[n,:] @ W) * dis[n]; writes BOTH g_h and g_agg ----
// Register tiling: 256 threads = FG f-groups x RS row-slots, RPT rows/thread,
// 4 f-columns per thread via float4 weight loads.
template <int FIN, int FOUT, int NPB, bool FROM_ACT>
__global__ void k_gemm(const float* __restrict__ Aext, const float* __restrict__ W) {
    const float* __restrict__ A = FROM_ACT ? (const float*)g_act : Aext;
    constexpr int FG  = FOUT / 4;     // f-groups (16 or 32)
    constexpr int RS  = 256 / FG;     // row slots (16 or 8)
    constexpr int RPT = NPB / RS;     // rows per thread
    __shared__ float sW[FIN * FOUT];
    __shared__ float sX[NPB * FIN];
    const int tid = threadIdx.x;
    // weights: vectorized when divisible by 4
    if constexpr ((FIN * FOUT) % 1024 == 0) {
        for (int i = tid; i < FIN * FOUT / 4; i += 256)
            reinterpret_cast<float4*>(sW)[i] = reinterpret_cast<const float4*>(W)[i];
    } else {
        for (int i = tid; i < FIN * FOUT; i += 256) sW[i] = W[i];
    }
    const int n0 = blockIdx.x * NPB;
    for (int i = tid; i < NPB * FIN; i += 256) {
        int nn = i / FIN, k = i % FIN;
        int n = n0 + nn;
        sX[i] = (n < NN) ? A[(size_t)n * FIN + k] : 0.f;
    }
    __syncthreads();
    const int fg = tid % FG;          // f = fg*4 .. fg*4+3
    const int rs = tid / FG;
    float4 acc[RPT];
    #pragma unroll
    for (int r = 0; r < RPT; r++) acc[r] = make_float4(0.f, 0.f, 0.f, 0.f);
    #pragma unroll
    for (int k = 0; k < FIN; k++) {
        float4 w = *reinterpret_cast<const float4*>(&sW[k * FOUT + fg * 4]);
        #pragma unroll
        for (int r = 0; r < RPT; r++) {
            float xv = sX[(rs + r * RS) * FIN + k];
            acc[r].x = fmaf(xv, w.x, acc[r].x);
            acc[r].y = fmaf(xv, w.y, acc[r].y);
            acc[r].z = fmaf(xv, w.z, acc[r].z);
            acc[r].w = fmaf(xv, w.w, acc[r].w);
        }
    }
    #pragma unroll
    for (int r = 0; r < RPT; r++) {
        int n = n0 + rs + r * RS;
        if (n >= NN) continue;
        float ds = g_dis[n];
        float4 o = make_float4(acc[r].x * ds, acc[r].y * ds, acc[r].z * ds, acc[r].w * ds);
        size_t off = (size_t)n * FOUT + fg * 4;
        *reinterpret_cast<float4*>(g_h + off)   = o;
        *reinterpret_cast<float4*>(g_agg + off) = o;   // accumulator init = self hs
    }
}

// ---- scatter: agg[dst] += hs[src] ----
__global__ void k_scatter64() {
    int t = blockIdx.x * blockDim.x + threadIdx.x;
    int e = t >> 4;
    if (e >= EE) return;
    int c = t & 15;
    int2 sd = g_edge[e];
    float4 v = *reinterpret_cast<const float4*>(g_h + (size_t)sd.x * 64 + c * 4);
    red_add_v4(g_agg + (size_t)sd.y * 64 + c * 4, v);
}
__global__ void k_scatter128() {
    int t = blockIdx.x * blockDim.x + threadIdx.x;
    int e = t >> 5;
    if (e >= EE) return;
    int c = t & 31;
    int2 sd = g_edge[e];
    float4 v = *reinterpret_cast<const float4*>(g_h + (size_t)sd.x * 128 + c * 4);
    red_add_v4(g_agg + (size_t)sd.y * 128 + c * 4, v);
}

// ---- epilogue layers 1/2: act = relu(bn(dis*agg + b)), vectorized ----
__global__ void k_epi64(const float* __restrict__ b, const float* __restrict__ g,
                        const float* __restrict__ be, const float* __restrict__ m,
                        const float* __restrict__ v) {
    int t = blockIdx.x * blockDim.x + threadIdx.x;
    int n = t >> 4;
    if (n >= NN) return;
    int c = t & 15;
    int f = c * 4;
    size_t i = (size_t)n * 64 + f;
    float dis = g_dis[n];
    float4 a  = *reinterpret_cast<const float4*>(g_agg + i);
    float4 bb = *reinterpret_cast<const float4*>(b + f);
    float4 gg = *reinterpret_cast<const float4*>(g + f);
    float4 bee = *reinterpret_cast<const float4*>(be + f);
    float4 mm = *reinterpret_cast<const float4*>(m + f);
    float4 vv = *reinterpret_cast<const float4*>(v + f);
    float4 o;
    o.x = fmaxf((dis * a.x + bb.x - mm.x) * (gg.x * rsqrtf(vv.x + 1e-5f)) + bee.x, 0.f);
    o.y = fmaxf((dis * a.y + bb.y - mm.y) * (gg.y * rsqrtf(vv.y + 1e-5f)) + bee.y, 0.f);
    o.z = fmaxf((dis * a.z + bb.z - mm.z) * (gg.z * rsqrtf(vv.z + 1e-5f)) + bee.z, 0.f);
    o.w = fmaxf((dis * a.w + bb.w - mm.w) * (gg.w * rsqrtf(vv.w + 1e-5f)) + bee.w, 0.f);
    *reinterpret_cast<float4*>(g_act + i) = o;
}

// ---- layer-3 epilogue fused with mean-pool accumulation + graph counts ----
__global__ void k_epi3(const float* __restrict__ b3, const void* __restrict__ batch) {
    int t = blockIdx.x * blockDim.x + threadIdx.x;
    int n = t >> 5;
    if (n >= NN) return;
    int c = t & 31;
    size_t i = (size_t)n * 128 + c * 4;
    float dis = g_dis[n];
    float4 a = *reinterpret_cast<const float4*>(g_agg + i);
    float4 bb = *reinterpret_cast<const float4*>(b3 + c * 4);
    float4 o;
    o.x = fmaxf(dis * a.x + bb.x, 0.f);
    o.y = fmaxf(dis * a.y + bb.y, 0.f);
    o.z = fmaxf(dis * a.z + bb.z, 0.f);
    o.w = fmaxf(dis * a.w + bb.w, 0.f);
    int bg = load_idx(batch, n);
    if ((unsigned)bg >= BB) bg = 0;
    red_add_v4(g_sums + bg * 128 + c * 4, o);
    if (c == 0) atomicAdd(&g_cnt[bg], 1.f);
}

// ---- finalize: out[b,f] = sums / max(cnt, 1) ----
__global__ void k_final(float* __restrict__ out) {
    int i = blockIdx.x * blockDim.x + threadIdx.x;
    if (i >= BB * 128) return;
    out[i] = g_sums[i] / fmaxf(g_cnt[i >> 7], 1.f);
}

extern "C" void kernel_launch(void* const* d_in, const int* in_sizes, int n_in,
                              void* d_out, int out_size) {
    const float* x   = (const float*)d_in[0];
    const void*  ei  = d_in[1];
    const void*  bat = d_in[2];
    const float* W1 = (const float*)d_in[3];
    const float* b1 = (const float*)d_in[4];
    const float* W2 = (const float*)d_in[5];
    const float* b2 = (const float*)d_in[6];
    const float* W3 = (const float*)d_in[7];
    const float* b3 = (const float*)d_in[8];
    const float* g1 = (const float*)d_in[9];
    const float* be1 = (const float*)d_in[10];
    const float* m1 = (const float*)d_in[11];
    const float* v1 = (const float*)d_in[12];
    const float* g2 = (const float*)d_in[13];
    const float* be2 = (const float*)d_in[14];
    const float* m2 = (const float*)d_in[15];
    const float* v2 = (const float*)d_in[16];

    const int TB = 256;

    k_init<<<(NN + TB - 1) / TB, TB>>>((const int*)ei);
    k_prep<<<(EE + TB - 1) / TB, TB>>>(ei);
    k_dis<<<(NN + TB - 1) / TB, TB>>>();

    // ---- layer 1: 22 -> 64 ----
    k_gemm<22, 64, 32, false><<<(NN + 31) / 32, TB>>>(x, W1);
    k_scatter64<<<(EE * 16 + TB - 1) / TB, TB>>>();
    k_epi64<<<(NN * 16 + TB - 1) / TB, TB>>>(b1, g1, be1, m1, v1);

    // ---- layer 2: 64 -> 64 ----
    k_gemm<64, 64, 32, true><<<(NN + 31) / 32, TB>>>(nullptr, W2);
    k_scatter64<<<(EE * 16 + TB - 1) / TB, TB>>>();
    k_epi64<<<(NN * 16 + TB - 1) / TB, TB>>>(b2, g2, be2, m2, v2);

    // ---- layer 3: 64 -> 128, fused pooling ----
    k_gemm<64, 128, 16, true><<<(NN + 15) / 16, TB>>>(nullptr, W3);
    k_scatter128<<<(int)(((long long)EE * 32 + TB - 1) / TB), TB>>>();
    k_epi3<<<(NN * 32 + TB - 1) / TB, TB>>>(b3, bat);
    k_final<<<(BB * 128 + TB - 1) / TB, TB>>>((float*)d_out);
}

// round 6
// speedup vs baseline: 2.3653x; 1.7975x over previous
#include <cuda_runtime.h>
#include <cuda_bf16.h>

#define NN 100000
#define EE 1600000
#define BB 256
#define NCH 98          // ceil(NN / 1024)

// ---- scratch (device globals; no allocation allowed) ----
__device__ __align__(128) float g_h[(size_t)NN * 128];    // hs = (A @ W) * dis[n]
__device__ __align__(128) float g_act[(size_t)NN * 128];  // layer activations
__device__ __align__(128) float g_dis[NN];                // rsqrt(deg+1)
__device__ int   g_deg[NN];                               // in-degree
__device__ int   g_off[NN];                               // CSR row offsets
__device__ int   g_cur[NN];                               // sort cursors
__device__ int   g_scan[NN];                              // block-local inclusive scan
__device__ int   g_bsum[NCH + 1];
__device__ int   g_boff[NCH + 1];
__device__ int   g_esrc[EE];                              // src ids grouped by dst
__device__ __align__(128) float g_sums[BB * 128];
__device__ float g_cnt[BB];
__device__ int   g_is64;

__device__ __forceinline__ void red_add_v4(float* addr, float4 v) {
    unsigned long long ga = (unsigned long long)__cvta_generic_to_global(addr);
    asm volatile("red.global.add.v4.f32 [%0], {%1,%2,%3,%4};"
                 :: "l"(ga), "f"(v.x), "f"(v.y), "f"(v.z), "f"(v.w) : "memory");
}

__device__ __forceinline__ int load_idx(const void* p, long long i) {
    return g_is64 ? (int)((const long long*)p)[i] : ((const int*)p)[i];
}

// ---- init: zero counters + dtype detection ----
__global__ void k_init(const int* __restrict__ raw) {
    int i = blockIdx.x * blockDim.x + threadIdx.x;
    if (i < NN) { g_deg[i] = 0; g_cur[i] = 0; }
    if (i < BB * 128) g_sums[i] = 0.f;
    if (i < BB) g_cnt[i] = 0.f;
    if (i == 0) {
        int nz = 0;
        for (int j = 1; j < 256; j += 2) nz += (raw[j] != 0);
        g_is64 = (nz == 0) ? 1 : 0;
    }
}

// ---- histogram of in-degrees ----
__global__ void k_hist(const void* __restrict__ ei) {
    int e = blockIdx.x * blockDim.x + threadIdx.x;
    if (e >= EE) return;
    int d = load_idx(ei, (long long)EE + e);
    if ((unsigned)d >= NN) d = 0;
    atomicAdd(&g_deg[d], 1);
}

// ---- scan stage 1: per-1024-chunk inclusive scan (Kogge-Stone) ----
__global__ void k_scan1() {
    __shared__ int s[1024];
    int t = threadIdx.x;
    int i = blockIdx.x * 1024 + t;
    int v = (i < NN) ? g_deg[i] : 0;
    s[t] = v;
    __syncthreads();
    #pragma unroll
    for (int d = 1; d < 1024; d <<= 1) {
        int add = (t >= d) ? s[t - d] : 0;
        __syncthreads();
        s[t] += add;
        __syncthreads();
    }
    if (i < NN) g_scan[i] = s[t];
    if (t == 1023) g_bsum[blockIdx.x] = s[1023];
}

// ---- scan stage 2: exclusive scan of chunk totals (tiny) ----
__global__ void k_scan2() {
    if (threadIdx.x == 0) {
        int run = 0;
        for (int j = 0; j < NCH; j++) { g_boff[j] = run; run += g_bsum[j]; }
    }
}

// ---- scan stage 3: finalize offsets + dis ----
__global__ void k_scan3() {
    int i = blockIdx.x * blockDim.x + threadIdx.x;
    if (i >= NN) return;
    int dg = g_deg[i];
    g_off[i] = g_boff[i >> 10] + g_scan[i] - dg;
    g_dis[i] = rsqrtf((float)dg + 1.f);
}

// ---- counting-sort edges by dst (src values into CSR slots) ----
__global__ void k_sort(const void* __restrict__ ei) {
    int e = blockIdx.x * blockDim.x + threadIdx.x;
    if (e >= EE) return;
    int s = load_idx(ei, e);
    int d = load_idx(ei, (long long)EE + e);
    if ((unsigned)s >= NN) s = 0;
    if ((unsigned)d >= NN) d = 0;
    int p = g_off[d] + atomicAdd(&g_cur[d], 1);
    g_esrc[p] = s;
}

// ---- GEMM: g_h[n,:] = (A[n,:] @ W) * dis[n] ----
template <int FIN, int FOUT, int NPB, bool FROM_ACT>
__global__ void k_gemm(const float* __restrict__ Aext, const float* __restrict__ W) {
    const float* __restrict__ A = FROM_ACT ? (const float*)g_act : Aext;
    constexpr int FG  = FOUT / 4;
    constexpr int RS  = 256 / FG;
    constexpr int RPT = NPB / RS;
    __shared__ float sW[FIN * FOUT];
    __shared__ float sX[NPB * FIN];
    const int tid = threadIdx.x;
    if constexpr ((FIN * FOUT) % 1024 == 0) {
        for (int i = tid; i < FIN * FOUT / 4; i += 256)
            reinterpret_cast<float4*>(sW)[i] = reinterpret_cast<const float4*>(W)[i];
    } else {
        for (int i = tid; i < FIN * FOUT; i += 256) sW[i] = W[i];
    }
    const int n0 = blockIdx.x * NPB;
    for (int i = tid; i < NPB * FIN; i += 256) {
        int nn = i / FIN, k = i % FIN;
        int n = n0 + nn;
        sX[i] = (n < NN) ? A[(size_t)n * FIN + k] : 0.f;
    }
    __syncthreads();
    const int fg = tid % FG;
    const int rs = tid / FG;
    float4 acc[RPT];
    #pragma unroll
    for (int r = 0; r < RPT; r++) acc[r] = make_float4(0.f, 0.f, 0.f, 0.f);
    #pragma unroll
    for (int k = 0; k < FIN; k++) {
        float4 w = *reinterpret_cast<const float4*>(&sW[k * FOUT + fg * 4]);
        #pragma unroll
        for (int r = 0; r < RPT; r++) {
            float xv = sX[(rs + r * RS) * FIN + k];
            acc[r].x = fmaf(xv, w.x, acc[r].x);
            acc[r].y = fmaf(xv, w.y, acc[r].y);
            acc[r].z = fmaf(xv, w.z, acc[r].z);
            acc[r].w = fmaf(xv, w.w, acc[r].w);
        }
    }
    #pragma unroll
    for (int r = 0; r < RPT; r++) {
        int n = n0 + rs + r * RS;
        if (n >= NN) continue;
        float ds = g_dis[n];
        float4 o = make_float4(acc[r].x * ds, acc[r].y * ds, acc[r].z * ds, acc[r].w * ds);
        *reinterpret_cast<float4*>(g_h + (size_t)n * FOUT + fg * 4) = o;
    }
}

// ---- fused aggregation + epilogue, 64-wide: 16 threads per node ----
__global__ void k_agg64(const float* __restrict__ b, const float* __restrict__ g,
                        const float* __restrict__ be, const float* __restrict__ m,
                        const float* __restrict__ v) {
    int t = blockIdx.x * blockDim.x + threadIdx.x;
    int n = t >> 4;
    if (n >= NN) return;
    int c = t & 15;
    int f = c * 4;
    // self term (hs[n])
    float4 acc = *reinterpret_cast<const float4*>(g_h + (size_t)n * 64 + f);
    int p = g_off[n];
    int end = p + g_deg[n];
    for (; p + 1 < end; p += 2) {
        int s0 = __ldg(&g_esrc[p]);
        int s1 = __ldg(&g_esrc[p + 1]);
        float4 v0 = *reinterpret_cast<const float4*>(g_h + (size_t)s0 * 64 + f);
        float4 v1 = *reinterpret_cast<const float4*>(g_h + (size_t)s1 * 64 + f);
        acc.x += v0.x; acc.y += v0.y; acc.z += v0.z; acc.w += v0.w;
        acc.x += v1.x; acc.y += v1.y; acc.z += v1.z; acc.w += v1.w;
    }
    if (p < end) {
        int s0 = __ldg(&g_esrc[p]);
        float4 v0 = *reinterpret_cast<const float4*>(g_h + (size_t)s0 * 64 + f);
        acc.x += v0.x; acc.y += v0.y; acc.z += v0.z; acc.w += v0.w;
    }
    float dis = g_dis[n];
    float4 bb  = *reinterpret_cast<const float4*>(b + f);
    float4 gg  = *reinterpret_cast<const float4*>(g + f);
    float4 bee = *reinterpret_cast<const float4*>(be + f);
    float4 mm  = *reinterpret_cast<const float4*>(m + f);
    float4 vv  = *reinterpret_cast<const float4*>(v + f);
    float4 o;
    o.x = fmaxf((dis * acc.x + bb.x - mm.x) * (gg.x * rsqrtf(vv.x + 1e-5f)) + bee.x, 0.f);
    o.y = fmaxf((dis * acc.y + bb.y - mm.y) * (gg.y * rsqrtf(vv.y + 1e-5f)) + bee.y, 0.f);
    o.z = fmaxf((dis * acc.z + bb.z - mm.z) * (gg.z * rsqrtf(vv.z + 1e-5f)) + bee.z, 0.f);
    o.w = fmaxf((dis * acc.w + bb.w - mm.w) * (gg.w * rsqrtf(vv.w + 1e-5f)) + bee.w, 0.f);
    *reinterpret_cast<float4*>(g_act + (size_t)n * 64 + f) = o;
}

// ---- fused aggregation + relu + mean-pool, 128-wide: 32 threads per node ----
__global__ void k_agg128(const float* __restrict__ b3, const void* __restrict__ batch) {
    int t = blockIdx.x * blockDim.x + threadIdx.x;
    int n = t >> 5;
    if (n >= NN) return;
    int c = t & 31;
    int f = c * 4;
    float4 acc = *reinterpret_cast<const float4*>(g_h + (size_t)n * 128 + f);
    int p = g_off[n];
    int end = p + g_deg[n];
    for (; p + 1 < end; p += 2) {
        int s0 = __ldg(&g_esrc[p]);
        int s1 = __ldg(&g_esrc[p + 1]);
        float4 v0 = *reinterpret_cast<const float4*>(g_h + (size_t)s0 * 128 + f);
        float4 v1 = *reinterpret_cast<const float4*>(g_h + (size_t)s1 * 128 + f);
        acc.x += v0.x; acc.y += v0.y; acc.z += v0.z; acc.w += v0.w;
        acc.x += v1.x; acc.y += v1.y; acc.z += v1.z; acc.w += v1.w;
    }
    if (p < end) {
        int s0 = __ldg(&g_esrc[p]);
        float4 v0 = *reinterpret_cast<const float4*>(g_h + (size_t)s0 * 128 + f);
        acc.x += v0.x; acc.y += v0.y; acc.z += v0.z; acc.w += v0.w;
    }
    float dis = g_dis[n];
    float4 bb = *reinterpret_cast<const float4*>(b3 + f);
    float4 o;
    o.x = fmaxf(dis * acc.x + bb.x, 0.f);
    o.y = fmaxf(dis * acc.y + bb.y, 0.f);
    o.z = fmaxf(dis * acc.z + bb.z, 0.f);
    o.w = fmaxf(dis * acc.w + bb.w, 0.f);
    int bg = load_idx(batch, n);
    if ((unsigned)bg >= BB) bg = 0;
    red_add_v4(g_sums + bg * 128 + f, o);
    if (c == 0) atomicAdd(&g_cnt[bg], 1.f);
}

// ---- finalize: out[b,f] = sums / max(cnt, 1) ----
__global__ void k_final(float* __restrict__ out) {
    int i = blockIdx.x * blockDim.x + threadIdx.x;
    if (i >= BB * 128) return;
    out[i] = g_sums[i] / fmaxf(g_cnt[i >> 7], 1.f);
}

extern "C" void kernel_launch(void* const* d_in, const int* in_sizes, int n_in,
                              void* d_out, int out_size) {
    const float* x   = (const float*)d_in[0];
    const void*  ei  = d_in[1];
    const void*  bat = d_in[2];
    const float* W1 = (const float*)d_in[3];
    const float* b1 = (const float*)d_in[4];
    const float* W2 = (const float*)d_in[5];
    const float* b2 = (const float*)d_in[6];
    const float* W3 = (const float*)d_in[7];
    const float* b3 = (const float*)d_in[8];
    const float* g1 = (const float*)d_in[9];
    const float* be1 = (const float*)d_in[10];
    const float* m1 = (const float*)d_in[11];
    const float* v1 = (const float*)d_in[12];
    const float* g2 = (const float*)d_in[13];
    const float* be2 = (const float*)d_in[14];
    const float* m2 = (const float*)d_in[15];
    const float* v2 = (const float*)d_in[16];

    const int TB = 256;

    // CSR construction
    k_init<<<(NN + TB - 1) / TB, TB>>>((const int*)ei);
    k_hist<<<(EE + TB - 1) / TB, TB>>>(ei);
    k_scan1<<<NCH, 1024>>>();
    k_scan2<<<1, 32>>>();
    k_scan3<<<(NN + TB - 1) / TB, TB>>>();
    k_sort<<<(EE + TB - 1) / TB, TB>>>(ei);

    // ---- layer 1: 22 -> 64 ----
    k_gemm<22, 64, 32, false><<<(NN + 31) / 32, TB>>>(x, W1);
    k_agg64<<<(NN * 16 + TB - 1) / TB, TB>>>(b1, g1, be1, m1, v1);

    // ---- layer 2: 64 -> 64 ----
    k_gemm<64, 64, 32, true><<<(NN + 31) / 32, TB>>>(nullptr, W2);
    k_agg64<<<(NN * 16 + TB - 1) / TB, TB>>>(b2, g2, be2, m2, v2);

    // ---- layer 3: 64 -> 128, fused pooling ----
    k_gemm<64, 128, 16, true><<<(NN + 15) / 16, TB>>>(nullptr, W3);
    k_agg128<<<(NN * 32 + TB - 1) / TB, TB>>>(b3, bat);
    k_final<<<(BB * 128 + TB - 1) / TB, TB>>>((float*)d_out);
}

// round 7
// speedup vs baseline: 2.4564x; 1.0385x over previous
#include <cuda_runtime.h>
#include <cuda_bf16.h>

#define NN 100000
#define EE 1600000
#define BB 256
#define NCH 98          // ceil(NN / 1024)

// ---- scratch (device globals; no allocation allowed) ----
__device__ __align__(128) float g_h[(size_t)NN * 128];            // fp32 hs
__device__ __align__(128) __nv_bfloat16 g_hb[(size_t)NN * 128];   // bf16 hs (gather path)
__device__ __align__(128) float g_act[(size_t)NN * 128];          // activations
__device__ __align__(128) float g_dis[NN];                        // rsqrt(deg+1)
__device__ int   g_deg[NN];
__device__ int   g_off[NN];
__device__ int   g_cur[NN];
__device__ int   g_scan[NN];
__device__ int   g_bsum[NCH + 1];
__device__ int   g_boff[NCH + 1];
__device__ int   g_esrc[EE];
__device__ __align__(128) float g_sums[BB * 128];
__device__ float g_cnt[BB];
__device__ int   g_is64;

__device__ __forceinline__ void red_add_v4(float* addr, float4 v) {
    unsigned long long ga = (unsigned long long)__cvta_generic_to_global(addr);
    asm volatile("red.global.add.v4.f32 [%0], {%1,%2,%3,%4};"
                 :: "l"(ga), "f"(v.x), "f"(v.y), "f"(v.z), "f"(v.w) : "memory");
}

__device__ __forceinline__ int load_idx(const void* p, long long i) {
    return g_is64 ? (int)((const long long*)p)[i] : ((const int*)p)[i];
}

// accumulate 8 bf16 (one uint4) into 8 fp32 accumulators
__device__ __forceinline__ void acc8_bf16(float* acc, uint4 v) {
    const __nv_bfloat162* b2 = reinterpret_cast<const __nv_bfloat162*>(&v);
    #pragma unroll
    for (int j = 0; j < 4; j++) {
        float2 f2 = __bfloat1622float2(b2[j]);
        acc[j * 2 + 0] += f2.x;
        acc[j * 2 + 1] += f2.y;
    }
}

// ---- init: zero counters + dtype detection ----
__global__ void k_init(const int* __restrict__ raw) {
    int i = blockIdx.x * blockDim.x + threadIdx.x;
    if (i < NN) g_deg[i] = 0;
    if (i < BB * 128) g_sums[i] = 0.f;
    if (i < BB) g_cnt[i] = 0.f;
    if (i == 0) {
        int nz = 0;
        for (int j = 1; j < 256; j += 2) nz += (raw[j] != 0);
        g_is64 = (nz == 0) ? 1 : 0;
    }
}

// ---- histogram of in-degrees ----
__global__ void k_hist(const void* __restrict__ ei) {
    int e = blockIdx.x * blockDim.x + threadIdx.x;
    if (e >= EE) return;
    int d = load_idx(ei, (long long)EE + e);
    if ((unsigned)d >= NN) d = 0;
    atomicAdd(&g_deg[d], 1);
}

// ---- scan stage 1: per-1024-chunk inclusive scan (Kogge-Stone) ----
__global__ void k_scan1() {
    __shared__ int s[1024];
    int t = threadIdx.x;
    int i = blockIdx.x * 1024 + t;
    int v = (i < NN) ? g_deg[i] : 0;
    s[t] = v;
    __syncthreads();
    #pragma unroll
    for (int d = 1; d < 1024; d <<= 1) {
        int add = (t >= d) ? s[t - d] : 0;
        __syncthreads();
        s[t] += add;
        __syncthreads();
    }
    if (i < NN) g_scan[i] = s[t];
    if (t == 1023) g_bsum[blockIdx.x] = s[1023];
}

// ---- scan stage 2: parallel exclusive scan of chunk totals ----
__global__ void k_scan2() {
    __shared__ int s[128];
    int t = threadIdx.x;
    int v = (t < NCH) ? g_bsum[t] : 0;
    s[t] = v;
    __syncthreads();
    #pragma unroll
    for (int d = 1; d < 128; d <<= 1) {
        int add = (t >= d) ? s[t - d] : 0;
        __syncthreads();
        s[t] += add;
        __syncthreads();
    }
    if (t < NCH) g_boff[t] = s[t] - v;   // exclusive
}

// ---- scan stage 3: finalize offsets + dis + seed sort cursor ----
__global__ void k_scan3() {
    int i = blockIdx.x * blockDim.x + threadIdx.x;
    if (i >= NN) return;
    int dg = g_deg[i];
    int off = g_boff[i >> 10] + g_scan[i] - dg;
    g_off[i] = off;
    g_cur[i] = off;
    g_dis[i] = rsqrtf((float)dg + 1.f);
}

// ---- counting-sort edges by dst ----
__global__ void k_sort(const void* __restrict__ ei) {
    int e = blockIdx.x * blockDim.x + threadIdx.x;
    if (e >= EE) return;
    int s = load_idx(ei, e);
    int d = load_idx(ei, (long long)EE + e);
    if ((unsigned)s >= NN) s = 0;
    if ((unsigned)d >= NN) d = 0;
    int p = atomicAdd(&g_cur[d], 1);
    g_esrc[p] = s;
}

// ---- GEMM: hs = (A @ W) * dis; writes fp32 g_h + bf16 g_hb ----
template <int FIN, int FOUT, int NPB, bool FROM_ACT>
__global__ void k_gemm(const float* __restrict__ Aext, const float* __restrict__ W) {
    const float* __restrict__ A = FROM_ACT ? (const float*)g_act : Aext;
    constexpr int FG  = FOUT / 4;
    constexpr int RS  = 256 / FG;
    constexpr int RPT = NPB / RS;
    __shared__ float sW[FIN * FOUT];
    __shared__ float sX[NPB * FIN];
    const int tid = threadIdx.x;
    if constexpr ((FIN * FOUT) % 1024 == 0) {
        for (int i = tid; i < FIN * FOUT / 4; i += 256)
            reinterpret_cast<float4*>(sW)[i] = reinterpret_cast<const float4*>(W)[i];
    } else {
        for (int i = tid; i < FIN * FOUT; i += 256) sW[i] = W[i];
    }
    const int n0 = blockIdx.x * NPB;
    for (int i = tid; i < NPB * FIN; i += 256) {
        int nn = i / FIN, k = i % FIN;
        int n = n0 + nn;
        sX[i] = (n < NN) ? A[(size_t)n * FIN + k] : 0.f;
    }
    __syncthreads();
    const int fg = tid % FG;
    const int rs = tid / FG;
    float4 acc[RPT];
    #pragma unroll
    for (int r = 0; r < RPT; r++) acc[r] = make_float4(0.f, 0.f, 0.f, 0.f);
    #pragma unroll
    for (int k = 0; k < FIN; k++) {
        float4 w = *reinterpret_cast<const float4*>(&sW[k * FOUT + fg * 4]);
        #pragma unroll
        for (int r = 0; r < RPT; r++) {
            float xv = sX[(rs + r * RS) * FIN + k];
            acc[r].x = fmaf(xv, w.x, acc[r].x);
            acc[r].y = fmaf(xv, w.y, acc[r].y);
            acc[r].z = fmaf(xv, w.z, acc[r].z);
            acc[r].w = fmaf(xv, w.w, acc[r].w);
        }
    }
    #pragma unroll
    for (int r = 0; r < RPT; r++) {
        int n = n0 + rs + r * RS;
        if (n >= NN) continue;
        float ds = g_dis[n];
        float4 o = make_float4(acc[r].x * ds, acc[r].y * ds, acc[r].z * ds, acc[r].w * ds);
        size_t off = (size_t)n * FOUT + fg * 4;
        *reinterpret_cast<float4*>(g_h + off) = o;
        __nv_bfloat162 p0 = __floats2bfloat162_rn(o.x, o.y);
        __nv_bfloat162 p1 = __floats2bfloat162_rn(o.z, o.w);
        uint2 pk;
        pk.x = *reinterpret_cast<unsigned*>(&p0);
        pk.y = *reinterpret_cast<unsigned*>(&p1);
        *reinterpret_cast<uint2*>(g_hb + off) = pk;
    }
}

// ---- fused aggregation + BN + ReLU, 64-wide: 8 threads/node, 8 cols each ----
__global__ void k_agg64(const float* __restrict__ b, const float* __restrict__ g,
                        const float* __restrict__ be, const float* __restrict__ m,
                        const float* __restrict__ v) {
    int t = blockIdx.x * blockDim.x + threadIdx.x;
    int n = t >> 3;
    if (n >= NN) return;
    int c = t & 7;
    int f = c * 8;
    float acc[8];
    {   // self term (fp32)
        float4 a0 = *reinterpret_cast<const float4*>(g_h + (size_t)n * 64 + f);
        float4 a1 = *reinterpret_cast<const float4*>(g_h + (size_t)n * 64 + f + 4);
        acc[0] = a0.x; acc[1] = a0.y; acc[2] = a0.z; acc[3] = a0.w;
        acc[4] = a1.x; acc[5] = a1.y; acc[6] = a1.z; acc[7] = a1.w;
    }
    const uint4* hb = reinterpret_cast<const uint4*>(g_hb);  // 8 uint4 per 64-row
    int p = g_off[n];
    int end = p + g_deg[n];
    for (; p + 1 < end; p += 2) {
        int s0 = __ldg(&g_esrc[p]);
        int s1 = __ldg(&g_esrc[p + 1]);
        uint4 v0 = __ldg(&hb[(size_t)s0 * 8 + c]);
        uint4 v1 = __ldg(&hb[(size_t)s1 * 8 + c]);
        acc8_bf16(acc, v0);
        acc8_bf16(acc, v1);
    }
    if (p < end) {
        int s0 = __ldg(&g_esrc[p]);
        uint4 v0 = __ldg(&hb[(size_t)s0 * 8 + c]);
        acc8_bf16(acc, v0);
    }
    float dis = g_dis[n];
    float out[8];
    #pragma unroll
    for (int j = 0; j < 8; j++) {
        int ff = f + j;
        float sc = g[ff] * rsqrtf(v[ff] + 1e-5f);
        out[j] = fmaxf((dis * acc[j] + b[ff] - m[ff]) * sc + be[ff], 0.f);
    }
    *reinterpret_cast<float4*>(g_act + (size_t)n * 64 + f)     = make_float4(out[0], out[1], out[2], out[3]);
    *reinterpret_cast<float4*>(g_act + (size_t)n * 64 + f + 4) = make_float4(out[4], out[5], out[6], out[7]);
}

// ---- fused aggregation + relu + mean-pool, 128-wide: 16 threads/node ----
__global__ void k_agg128(const float* __restrict__ b3, const void* __restrict__ batch) {
    int t = blockIdx.x * blockDim.x + threadIdx.x;
    int n = t >> 4;
    if (n >= NN) return;
    int c = t & 15;
    int f = c * 8;
    float acc[8];
    {
        float4 a0 = *reinterpret_cast<const float4*>(g_h + (size_t)n * 128 + f);
        float4 a1 = *reinterpret_cast<const float4*>(g_h + (size_t)n * 128 + f + 4);
        acc[0] = a0.x; acc[1] = a0.y; acc[2] = a0.z; acc[3] = a0.w;
        acc[4] = a1.x; acc[5] = a1.y; acc[6] = a1.z; acc[7] = a1.w;
    }
    const uint4* hb = reinterpret_cast<const uint4*>(g_hb);  // 16 uint4 per 128-row
    int p = g_off[n];
    int end = p + g_deg[n];
    for (; p + 1 < end; p += 2) {
        int s0 = __ldg(&g_esrc[p]);
        int s1 = __ldg(&g_esrc[p + 1]);
        uint4 v0 = __ldg(&hb[(size_t)s0 * 16 + c]);
        uint4 v1 = __ldg(&hb[(size_t)s1 * 16 + c]);
        acc8_bf16(acc, v0);
        acc8_bf16(acc, v1);
    }
    if (p < end) {
        int s0 = __ldg(&g_esrc[p]);
        uint4 v0 = __ldg(&hb[(size_t)s0 * 16 + c]);
        acc8_bf16(acc, v0);
    }
    float dis = g_dis[n];
    float4 o0, o1;
    o0.x = fmaxf(dis * acc[0] + b3[f + 0], 0.f);
    o0.y = fmaxf(dis * acc[1] + b3[f + 1], 0.f);
    o0.z = fmaxf(dis * acc[2] + b3[f + 2], 0.f);
    o0.w = fmaxf(dis * acc[3] + b3[f + 3], 0.f);
    o1.x = fmaxf(dis * acc[4] + b3[f + 4], 0.f);
    o1.y = fmaxf(dis * acc[5] + b3[f + 5], 0.f);
    o1.z = fmaxf(dis * acc[6] + b3[f + 6], 0.f);
    o1.w = fmaxf(dis * acc[7] + b3[f + 7], 0.f);
    int bg = load_idx(batch, n);
    if ((unsigned)bg >= BB) bg = 0;
    red_add_v4(g_sums + bg * 128 + f,     o0);
    red_add_v4(g_sums + bg * 128 + f + 4, o1);
    if (c == 0) atomicAdd(&g_cnt[bg], 1.f);
}

// ---- finalize: out[b,f] = sums / max(cnt, 1) ----
__global__ void k_final(float* __restrict__ out) {
    int i = blockIdx.x * blockDim.x + threadIdx.x;
    if (i >= BB * 128) return;
    out[i] = g_sums[i] / fmaxf(g_cnt[i >> 7], 1.f);
}

extern "C" void kernel_launch(void* const* d_in, const int* in_sizes, int n_in,
                              void* d_out, int out_size) {
    const float* x   = (const float*)d_in[0];
    const void*  ei  = d_in[1];
    const void*  bat = d_in[2];
    const float* W1 = (const float*)d_in[3];
    const float* b1 = (const float*)d_in[4];
    const float* W2 = (const float*)d_in[5];
    const float* b2 = (const float*)d_in[6];
    const float* W3 = (const float*)d_in[7];
    const float* b3 = (const float*)d_in[8];
    const float* g1 = (const float*)d_in[9];
    const float* be1 = (const float*)d_in[10];
    const float* m1 = (const float*)d_in[11];
    const float* v1 = (const float*)d_in[12];
    const float* g2 = (const float*)d_in[13];
    const float* be2 = (const float*)d_in[14];
    const float* m2 = (const float*)d_in[15];
    const float* v2 = (const float*)d_in[16];

    const int TB = 256;

    // CSR construction
    k_init<<<(NN + TB - 1) / TB, TB>>>((const int*)ei);
    k_hist<<<(EE + TB - 1) / TB, TB>>>(ei);
    k_scan1<<<NCH, 1024>>>();
    k_scan2<<<1, 128>>>();
    k_scan3<<<(NN + TB - 1) / TB, TB>>>();
    k_sort<<<(EE + TB - 1) / TB, TB>>>(ei);

    // ---- layer 1: 22 -> 64 ----
    k_gemm<22, 64, 32, false><<<(NN + 31) / 32, TB>>>(x, W1);
    k_agg64<<<(NN * 8 + TB - 1) / TB, TB>>>(b1, g1, be1, m1, v1);

    // ---- layer 2: 64 -> 64 ----
    k_gemm<64, 64, 32, true><<<(NN + 31) / 32, TB>>>(nullptr, W2);
    k_agg64<<<(NN * 8 + TB - 1) / TB, TB>>>(b2, g2, be2, m2, v2);

    // ---- layer 3: 64 -> 128, fused pooling ----
    k_gemm<64, 128, 16, true><<<(NN + 15) / 16, TB>>>(nullptr, W3);
    k_agg128<<<(NN * 16 + TB - 1) / TB, TB>>>(b3, bat);
    k_final<<<(BB * 128 + TB - 1) / TB, TB>>>((float*)d_out);
}